// round 1
// baseline (speedup 1.0000x reference)
#include <cuda_runtime.h>
#include <cuda_bf16.h>

// ---------------------------------------------------------------------------
// Problem constants (fixed shapes per reference)
// ---------------------------------------------------------------------------
#define MAX_N 100000
#define MAX_E 1600000
#define MAX_G 256

// Scratch (static device globals; no runtime allocation allowed)
__device__ float g_bufA[MAX_N * 216];
__device__ float g_bufB[MAX_N * 216];
__device__ float g_dinv[MAX_N];
__device__ float g_norm[MAX_E];
__device__ float g_pooled[MAX_G * 216];
__device__ float g_fc1[MAX_G * 1024];

// ---------------------------------------------------------------------------
// Degree / normalization
// ---------------------------------------------------------------------------
__global__ void init_deg_kernel(float* deg, int N) {
    int i = blockIdx.x * blockDim.x + threadIdx.x;
    if (i < N) deg[i] = 1.0f;  // self-loop contributes 1
}

__global__ void accum_deg_kernel(const int* __restrict__ col, float* deg, int E) {
    int i = blockIdx.x * blockDim.x + threadIdx.x;
    if (i < E) atomicAdd(&deg[col[i]], 1.0f);
}

__global__ void rsqrt_kernel(float* deg, int N) {
    int i = blockIdx.x * blockDim.x + threadIdx.x;
    if (i < N) deg[i] = rsqrtf(deg[i]);  // deg >= 1 always
}

__global__ void norm_kernel(const int* __restrict__ row, const int* __restrict__ col,
                            const float* __restrict__ dinv, float* __restrict__ norm, int E) {
    int i = blockIdx.x * blockDim.x + threadIdx.x;
    if (i < E) norm[i] = dinv[row[i]] * dinv[col[i]];
}

// ---------------------------------------------------------------------------
// Generic register-tiled SGEMM: C[M,Nc] = op(A)[M,K] @ B[K,Nc] (+bias)(+relu)
// BM=BN=64, BK=16, 256 threads, 4x4 micro-tile per thread.
// ---------------------------------------------------------------------------
template <bool RELU_IN, bool RELU_OUT, bool BIAS>
__global__ void gemm_kernel(const float* __restrict__ A, const float* __restrict__ B,
                            const float* __restrict__ bias, float* __restrict__ C,
                            int M, int K, int Nc) {
    const int BM = 64, BN = 64, BK = 16;
    __shared__ float As[BK][BM];
    __shared__ float Bs[BK][BN + 1];

    int block_row = blockIdx.y * BM;
    int block_col = blockIdx.x * BN;
    int tid = threadIdx.x;          // 0..255
    int tr = tid / 16;              // 0..15
    int tc = tid % 16;              // 0..15

    float acc[4][4] = {};

    for (int k0 = 0; k0 < K; k0 += BK) {
        // load A tile (BM x BK)
        #pragma unroll
        for (int i = tid; i < BM * BK; i += 256) {
            int r = i / BK, c = i % BK;
            int gr = block_row + r, gk = k0 + c;
            float v = 0.f;
            if (gr < M && gk < K) {
                v = A[(long long)gr * K + gk];
                if (RELU_IN) v = fmaxf(v, 0.f);
            }
            As[c][r] = v;
        }
        // load B tile (BK x BN)
        #pragma unroll
        for (int i = tid; i < BK * BN; i += 256) {
            int r = i / BN, c = i % BN;
            int gk = k0 + r, gc = block_col + c;
            Bs[r][c] = (gk < K && gc < Nc) ? B[(long long)gk * Nc + gc] : 0.f;
        }
        __syncthreads();

        #pragma unroll
        for (int k = 0; k < BK; k++) {
            float a[4], b[4];
            #pragma unroll
            for (int i = 0; i < 4; i++) a[i] = As[k][tr * 4 + i];
            #pragma unroll
            for (int j = 0; j < 4; j++) b[j] = Bs[k][tc * 4 + j];
            #pragma unroll
            for (int i = 0; i < 4; i++)
                #pragma unroll
                for (int j = 0; j < 4; j++)
                    acc[i][j] += a[i] * b[j];
        }
        __syncthreads();
    }

    #pragma unroll
    for (int i = 0; i < 4; i++) {
        int gr = block_row + tr * 4 + i;
        if (gr >= M) continue;
        #pragma unroll
        for (int j = 0; j < 4; j++) {
            int gc = block_col + tc * 4 + j;
            if (gc >= Nc) continue;
            float v = acc[i][j];
            if (BIAS) v += bias[gc];
            if (RELU_OUT) v = fmaxf(v, 0.f);
            C[(long long)gr * Nc + gc] = v;
        }
    }
}

// ---------------------------------------------------------------------------
// Scatter: out[v] = h[v]*dinv[v]^2 + bias  (self-loop + bias init)
// ---------------------------------------------------------------------------
__global__ void scatter_init_kernel(const float* __restrict__ h, const float* __restrict__ dinv,
                                    const float* __restrict__ bias, float* __restrict__ out,
                                    int N, int F) {
    int idx = blockIdx.x * blockDim.x + threadIdx.x;
    if (idx >= N * F) return;
    int v = idx / F, f = idx % F;
    float d = dinv[v];
    out[idx] = h[idx] * d * d + bias[f];
}

// Edge scatter-add: out[col[e]] += h[row[e]] * norm[e], vectorized by V floats.
template <int V>
__global__ void scatter_edges_kernel(const float* __restrict__ h, const int* __restrict__ row,
                                     const int* __restrict__ col, const float* __restrict__ norm,
                                     float* __restrict__ out, int E, int F) {
    int chunks = F / V;
    int idx = blockIdx.x * blockDim.x + threadIdx.x;
    if (idx >= E * chunks) return;
    int e = idx / chunks;
    int c = idx % chunks;
    int r = row[e];
    int cl = col[e];
    float nm = norm[e];
    const float* src = h + (long long)r * F + c * V;
    float* dst = out + (long long)cl * F + c * V;
    if (V == 4) {
        float4 v = *reinterpret_cast<const float4*>(src);
        atomicAdd(dst + 0, v.x * nm);
        atomicAdd(dst + 1, v.y * nm);
        atomicAdd(dst + 2, v.z * nm);
        atomicAdd(dst + 3, v.w * nm);
    } else {
        float2 v = *reinterpret_cast<const float2*>(src);
        atomicAdd(dst + 0, v.x * nm);
        atomicAdd(dst + 1, v.y * nm);
    }
}

// ---------------------------------------------------------------------------
// Per-graph mean pool with relu on input. One block per graph; batch is sorted.
// ---------------------------------------------------------------------------
__global__ void pool_kernel(const float* __restrict__ h, const int* __restrict__ batch,
                            float* __restrict__ pooled, int N, int F) {
    int g = blockIdx.x;
    // lower_bound(batch, g) and lower_bound(batch, g+1)
    int lo = 0, hi = N;
    while (lo < hi) { int m = (lo + hi) >> 1; if (batch[m] < g) lo = m + 1; else hi = m; }
    int start = lo;
    lo = start; hi = N;
    while (lo < hi) { int m = (lo + hi) >> 1; if (batch[m] < g + 1) lo = m + 1; else hi = m; }
    int end = lo;

    int f = threadIdx.x;
    if (f >= F) return;
    float acc = 0.f;
    for (int v = start; v < end; v++)
        acc += fmaxf(h[(long long)v * F + f], 0.f);
    float cnt = (float)(end - start);
    pooled[g * F + f] = acc / fmaxf(cnt, 1.0f);
}

// ---------------------------------------------------------------------------
// Launch
// ---------------------------------------------------------------------------
static inline dim3 gemm_grid(int M, int Nc) {
    return dim3((Nc + 63) / 64, (M + 63) / 64);
}

extern "C" void kernel_launch(void* const* d_in, const int* in_sizes, int n_in,
                              void* d_out, int out_size) {
    const float* x    = (const float*)d_in[0];
    const int*   ei   = (const int*)d_in[1];
    const int*   batch= (const int*)d_in[2];
    const float* W1   = (const float*)d_in[3];
    const float* b1   = (const float*)d_in[4];
    const float* W2   = (const float*)d_in[5];
    const float* b2   = (const float*)d_in[6];
    const float* W3   = (const float*)d_in[7];
    const float* b3   = (const float*)d_in[8];
    const float* Wf1  = (const float*)d_in[9];
    const float* bf1  = (const float*)d_in[10];
    const float* Wf2  = (const float*)d_in[11];
    const float* bf2  = (const float*)d_in[12];

    int N = in_sizes[0] / 54;
    int E = in_sizes[1] / 2;
    int G = out_size / 128;
    const int* row = ei;
    const int* col = ei + E;

    float *bufA, *bufB, *dinv, *norm, *pooled, *fc1;
    cudaGetSymbolAddress((void**)&bufA, g_bufA);
    cudaGetSymbolAddress((void**)&bufB, g_bufB);
    cudaGetSymbolAddress((void**)&dinv, g_dinv);
    cudaGetSymbolAddress((void**)&norm, g_norm);
    cudaGetSymbolAddress((void**)&pooled, g_pooled);
    cudaGetSymbolAddress((void**)&fc1, g_fc1);

    const int T = 256;

    // --- GCN normalization ---
    init_deg_kernel<<<(N + T - 1) / T, T>>>(dinv, N);
    accum_deg_kernel<<<(E + T - 1) / T, T>>>(col, dinv, E);
    rsqrt_kernel<<<(N + T - 1) / T, T>>>(dinv, N);
    norm_kernel<<<(E + T - 1) / T, T>>>(row, col, dinv, norm, E);

    // --- Layer 1: 54 -> 54 ---
    gemm_kernel<false, false, false><<<gemm_grid(N, 54), 256>>>(x, W1, nullptr, bufA, N, 54, 54);
    scatter_init_kernel<<<(N * 54 + T - 1) / T, T>>>(bufA, dinv, b1, bufB, N, 54);
    {
        int total = E * (54 / 2);
        scatter_edges_kernel<2><<<(total + T - 1) / T, T>>>(bufA, row, col, norm, bufB, E, 54);
    }

    // --- Layer 2: 54 -> 108 (relu on input fused into GEMM) ---
    gemm_kernel<true, false, false><<<gemm_grid(N, 108), 256>>>(bufB, W2, nullptr, bufA, N, 54, 108);
    scatter_init_kernel<<<(N * 108 + T - 1) / T, T>>>(bufA, dinv, b2, bufB, N, 108);
    {
        int total = E * (108 / 4);
        scatter_edges_kernel<4><<<(total + T - 1) / T, T>>>(bufA, row, col, norm, bufB, E, 108);
    }

    // --- Layer 3: 108 -> 216 ---
    gemm_kernel<true, false, false><<<gemm_grid(N, 216), 256>>>(bufB, W3, nullptr, bufA, N, 108, 216);
    scatter_init_kernel<<<(N * 216 + T - 1) / T, T>>>(bufA, dinv, b3, bufB, N, 216);
    {
        int total = E * (216 / 4);
        scatter_edges_kernel<4><<<(total + T - 1) / T, T>>>(bufA, row, col, norm, bufB, E, 216);
    }

    // --- Global mean pool (relu fused) ---
    pool_kernel<<<G, 224>>>(bufB, batch, pooled, N, 216);

    // --- MLP head ---
    gemm_kernel<false, true, true><<<gemm_grid(G, 1024), 256>>>(pooled, Wf1, bf1, fc1, G, 216, 1024);
    gemm_kernel<false, false, true><<<gemm_grid(G, 128), 256>>>(fc1, Wf2, bf2, (float*)d_out, G, 1024, 128);
}

// round 2
// speedup vs baseline: 2.1367x; 2.1367x over previous
#include <cuda_runtime.h>
#include <cuda_bf16.h>

#define MAX_N 100000
#define MAX_E 1600000
#define MAX_G 256

// ---------------------------------------------------------------------------
// Static scratch (no runtime allocation allowed)
// ---------------------------------------------------------------------------
__device__ float g_bufA[MAX_N * 216];   // aggregation buffer (max F=108 used) / gemm in
__device__ float g_bufB[MAX_N * 216];   // hidden activations (max F=216)
__device__ float g_dinv[MAX_N];
__device__ float g_pooled[MAX_G * 216];
__device__ float g_fc1[MAX_G * 1024];
__device__ int   g_counts[MAX_N];
__device__ int   g_indptr[MAX_N + 1];
__device__ int   g_cursor[MAX_N];
__device__ int   g_csrc[MAX_E];
__device__ float g_cnorm[MAX_E];

// ---------------------------------------------------------------------------
// CSR construction
// ---------------------------------------------------------------------------
__global__ void zero_counts_kernel(int* counts, int N) {
    int i = blockIdx.x * blockDim.x + threadIdx.x;
    if (i < N) counts[i] = 0;
}

__global__ void count_kernel(const int* __restrict__ col, int* counts, int E) {
    int i = blockIdx.x * blockDim.x + threadIdx.x;
    if (i < E) atomicAdd(&counts[col[i]], 1);
}

__global__ void dinv_kernel(const int* __restrict__ counts, float* __restrict__ dinv, int N) {
    int i = blockIdx.x * blockDim.x + threadIdx.x;
    if (i < N) dinv[i] = rsqrtf((float)(counts[i] + 1));  // +1 self-loop
}

// Single-block scan: indptr = exclusive_scan(counts), cursor = indptr copy.
__global__ void scan_kernel(const int* __restrict__ counts, int* __restrict__ indptr,
                            int* __restrict__ cursor, int N) {
    __shared__ int ssum[1024];
    int t = threadIdx.x;
    int chunk = (N + 1023) / 1024;
    int lo = t * chunk;
    int hi = lo + chunk; if (hi > N) hi = N; if (lo > N) lo = N;
    int s = 0;
    for (int i = lo; i < hi; i++) s += counts[i];
    ssum[t] = s;
    __syncthreads();
    for (int off = 1; off < 1024; off <<= 1) {
        int v = (t >= off) ? ssum[t - off] : 0;
        __syncthreads();
        ssum[t] += v;
        __syncthreads();
    }
    int run = (t == 0) ? 0 : ssum[t - 1];
    for (int i = lo; i < hi; i++) {
        indptr[i] = run;
        cursor[i] = run;
        run += counts[i];
    }
    if (t == 1023) indptr[N] = run;
}

__global__ void fill_kernel(const int* __restrict__ row, const int* __restrict__ col,
                            const float* __restrict__ dinv, int* cursor,
                            int* __restrict__ csrc, float* __restrict__ cnorm, int E) {
    int e = blockIdx.x * blockDim.x + threadIdx.x;
    if (e >= E) return;
    int r = row[e], c = col[e];
    int pos = atomicAdd(&cursor[c], 1);
    csrc[pos] = r;
    cnorm[pos] = dinv[r] * dinv[c];
}

// ---------------------------------------------------------------------------
// CSR gather aggregation: out[v] = sum_{e: col=v} norm[e]*h[src[e]] + dinv[v]^2 * h[v]
// One warp per node. F=54: float2 lanes 0..26. F=108: float4 lanes 0..26.
// ---------------------------------------------------------------------------
__global__ void gather54_kernel(const float* __restrict__ h, const int* __restrict__ indptr,
                                const int* __restrict__ csrc, const float* __restrict__ cnorm,
                                const float* __restrict__ dinv, float* __restrict__ out, int N) {
    const int F = 54, NL = 27;
    int warp = (blockIdx.x * blockDim.x + threadIdx.x) >> 5;
    int lane = threadIdx.x & 31;
    if (warp >= N) return;
    int v = warp;
    int s = indptr[v], e = indptr[v + 1];
    float2 a0 = {0.f, 0.f}, a1 = {0.f, 0.f};
    bool act = lane < NL;
    int i = s;
    for (; i + 1 < e; i += 2) {
        int s0 = csrc[i], s1 = csrc[i + 1];
        float n0 = cnorm[i], n1 = cnorm[i + 1];
        if (act) {
            float2 x0 = *reinterpret_cast<const float2*>(h + (size_t)s0 * F + lane * 2);
            float2 x1 = *reinterpret_cast<const float2*>(h + (size_t)s1 * F + lane * 2);
            a0.x += n0 * x0.x; a0.y += n0 * x0.y;
            a1.x += n1 * x1.x; a1.y += n1 * x1.y;
        }
    }
    if (i < e) {
        int s0 = csrc[i];
        float n0 = cnorm[i];
        if (act) {
            float2 x0 = *reinterpret_cast<const float2*>(h + (size_t)s0 * F + lane * 2);
            a0.x += n0 * x0.x; a0.y += n0 * x0.y;
        }
    }
    if (act) {
        float d = dinv[v]; float dd = d * d;
        float2 xv = *reinterpret_cast<const float2*>(h + (size_t)v * F + lane * 2);
        float2 r;
        r.x = a0.x + a1.x + dd * xv.x;
        r.y = a0.y + a1.y + dd * xv.y;
        *reinterpret_cast<float2*>(out + (size_t)v * F + lane * 2) = r;
    }
}

__global__ void gather108_kernel(const float* __restrict__ h, const int* __restrict__ indptr,
                                 const int* __restrict__ csrc, const float* __restrict__ cnorm,
                                 const float* __restrict__ dinv, float* __restrict__ out, int N) {
    const int F = 108, NL = 27;
    int warp = (blockIdx.x * blockDim.x + threadIdx.x) >> 5;
    int lane = threadIdx.x & 31;
    if (warp >= N) return;
    int v = warp;
    int s = indptr[v], e = indptr[v + 1];
    float4 a0 = {0.f, 0.f, 0.f, 0.f}, a1 = {0.f, 0.f, 0.f, 0.f};
    bool act = lane < NL;
    int i = s;
    for (; i + 1 < e; i += 2) {
        int s0 = csrc[i], s1 = csrc[i + 1];
        float n0 = cnorm[i], n1 = cnorm[i + 1];
        if (act) {
            float4 x0 = *reinterpret_cast<const float4*>(h + (size_t)s0 * F + lane * 4);
            float4 x1 = *reinterpret_cast<const float4*>(h + (size_t)s1 * F + lane * 4);
            a0.x += n0 * x0.x; a0.y += n0 * x0.y; a0.z += n0 * x0.z; a0.w += n0 * x0.w;
            a1.x += n1 * x1.x; a1.y += n1 * x1.y; a1.z += n1 * x1.z; a1.w += n1 * x1.w;
        }
    }
    if (i < e) {
        int s0 = csrc[i];
        float n0 = cnorm[i];
        if (act) {
            float4 x0 = *reinterpret_cast<const float4*>(h + (size_t)s0 * F + lane * 4);
            a0.x += n0 * x0.x; a0.y += n0 * x0.y; a0.z += n0 * x0.z; a0.w += n0 * x0.w;
        }
    }
    if (act) {
        float d = dinv[v]; float dd = d * d;
        float4 xv = *reinterpret_cast<const float4*>(h + (size_t)v * F + lane * 4);
        float4 r;
        r.x = a0.x + a1.x + dd * xv.x;
        r.y = a0.y + a1.y + dd * xv.y;
        r.z = a0.z + a1.z + dd * xv.z;
        r.w = a0.w + a1.w + dd * xv.w;
        *reinterpret_cast<float4*>(out + (size_t)v * F + lane * 4) = r;
    }
}

// ---------------------------------------------------------------------------
// Tiled SGEMM: C = A[M,K] @ B[K,Nc] (+bias)(+relu). Vectorized LDS.128 fragments.
// ---------------------------------------------------------------------------
template <bool RELU_OUT, bool BIAS>
__global__ void gemm_kernel(const float* __restrict__ A, const float* __restrict__ B,
                            const float* __restrict__ bias, float* __restrict__ C,
                            int M, int K, int Nc) {
    const int BM = 64, BN = 64, BK = 16;
    __shared__ __align__(16) float As[BK][BM];
    __shared__ __align__(16) float Bs[BK][BN];

    int block_row = blockIdx.y * BM;
    int block_col = blockIdx.x * BN;
    int tid = threadIdx.x;
    int tr = tid / 16;
    int tc = tid % 16;

    float acc[4][4] = {};

    for (int k0 = 0; k0 < K; k0 += BK) {
        #pragma unroll
        for (int i = tid; i < BM * BK; i += 256) {
            int r = i / BK, c = i % BK;
            int gr = block_row + r, gk = k0 + c;
            As[c][r] = (gr < M && gk < K) ? A[(size_t)gr * K + gk] : 0.f;
        }
        #pragma unroll
        for (int i = tid; i < BK * BN; i += 256) {
            int r = i / BN, c = i % BN;
            int gk = k0 + r, gc = block_col + c;
            Bs[r][c] = (gk < K && gc < Nc) ? B[(size_t)gk * Nc + gc] : 0.f;
        }
        __syncthreads();

        #pragma unroll
        for (int k = 0; k < BK; k++) {
            float4 a = *reinterpret_cast<const float4*>(&As[k][tr * 4]);
            float4 b = *reinterpret_cast<const float4*>(&Bs[k][tc * 4]);
            float av[4] = {a.x, a.y, a.z, a.w};
            float bv[4] = {b.x, b.y, b.z, b.w};
            #pragma unroll
            for (int i = 0; i < 4; i++)
                #pragma unroll
                for (int j = 0; j < 4; j++)
                    acc[i][j] += av[i] * bv[j];
        }
        __syncthreads();
    }

    #pragma unroll
    for (int i = 0; i < 4; i++) {
        int gr = block_row + tr * 4 + i;
        if (gr >= M) continue;
        #pragma unroll
        for (int j = 0; j < 4; j++) {
            int gc = block_col + tc * 4 + j;
            if (gc >= Nc) continue;
            float v = acc[i][j];
            if (BIAS) v += bias[gc];
            if (RELU_OUT) v = fmaxf(v, 0.f);
            C[(size_t)gr * Nc + gc] = v;
        }
    }
}

// ---------------------------------------------------------------------------
// Per-graph mean pool (h already relu'd). One block per graph, sorted batch.
// ---------------------------------------------------------------------------
__global__ void pool_kernel(const float* __restrict__ h, const int* __restrict__ batch,
                            float* __restrict__ pooled, int N, int F) {
    int g = blockIdx.x;
    int lo = 0, hi = N;
    while (lo < hi) { int m = (lo + hi) >> 1; if (batch[m] < g) lo = m + 1; else hi = m; }
    int start = lo;
    lo = start; hi = N;
    while (lo < hi) { int m = (lo + hi) >> 1; if (batch[m] < g + 1) lo = m + 1; else hi = m; }
    int end = lo;

    int f = threadIdx.x;
    if (f >= F) return;
    float acc = 0.f;
    for (int v = start; v < end; v++)
        acc += h[(size_t)v * F + f];
    float cnt = (float)(end - start);
    pooled[g * F + f] = acc / fmaxf(cnt, 1.0f);
}

// ---------------------------------------------------------------------------
// Launch
// ---------------------------------------------------------------------------
static inline dim3 gemm_grid(int M, int Nc) {
    return dim3((Nc + 63) / 64, (M + 63) / 64);
}

extern "C" void kernel_launch(void* const* d_in, const int* in_sizes, int n_in,
                              void* d_out, int out_size) {
    const float* x    = (const float*)d_in[0];
    const int*   ei   = (const int*)d_in[1];
    const int*   batch= (const int*)d_in[2];
    const float* W1   = (const float*)d_in[3];
    const float* b1   = (const float*)d_in[4];
    const float* W2   = (const float*)d_in[5];
    const float* b2   = (const float*)d_in[6];
    const float* W3   = (const float*)d_in[7];
    const float* b3   = (const float*)d_in[8];
    const float* Wf1  = (const float*)d_in[9];
    const float* bf1  = (const float*)d_in[10];
    const float* Wf2  = (const float*)d_in[11];
    const float* bf2  = (const float*)d_in[12];

    int N = in_sizes[0] / 54;
    int E = in_sizes[1] / 2;
    int G = out_size / 128;
    const int* row = ei;
    const int* col = ei + E;

    float *bufA, *bufB, *dinv, *pooled, *fc1, *cnorm;
    int *counts, *indptr, *cursor, *csrc;
    cudaGetSymbolAddress((void**)&bufA, g_bufA);
    cudaGetSymbolAddress((void**)&bufB, g_bufB);
    cudaGetSymbolAddress((void**)&dinv, g_dinv);
    cudaGetSymbolAddress((void**)&pooled, g_pooled);
    cudaGetSymbolAddress((void**)&fc1, g_fc1);
    cudaGetSymbolAddress((void**)&counts, g_counts);
    cudaGetSymbolAddress((void**)&indptr, g_indptr);
    cudaGetSymbolAddress((void**)&cursor, g_cursor);
    cudaGetSymbolAddress((void**)&csrc, g_csrc);
    cudaGetSymbolAddress((void**)&cnorm, g_cnorm);

    const int T = 256;
    int gatherGrid = (N + 7) / 8;  // 8 warps per 256-thread block

    // --- CSR build + normalization ---
    zero_counts_kernel<<<(N + T - 1) / T, T>>>(counts, N);
    count_kernel<<<(E + T - 1) / T, T>>>(col, counts, E);
    dinv_kernel<<<(N + T - 1) / T, T>>>(counts, dinv, N);
    scan_kernel<<<1, 1024>>>(counts, indptr, cursor, N);
    fill_kernel<<<(E + T - 1) / T, T>>>(row, col, dinv, cursor, csrc, cnorm, E);

    // --- Layer 1: agg(x) @ W1 + b1, relu ---
    gather54_kernel<<<gatherGrid, T>>>(x, indptr, csrc, cnorm, dinv, bufA, N);
    gemm_kernel<true, true><<<gemm_grid(N, 54), 256>>>(bufA, W1, b1, bufB, N, 54, 54);

    // --- Layer 2: agg(h1) @ W2 + b2, relu ---
    gather54_kernel<<<gatherGrid, T>>>(bufB, indptr, csrc, cnorm, dinv, bufA, N);
    gemm_kernel<true, true><<<gemm_grid(N, 108), 256>>>(bufA, W2, b2, bufB, N, 54, 108);

    // --- Layer 3: agg(h2) @ W3 + b3, relu ---
    gather108_kernel<<<gatherGrid, T>>>(bufB, indptr, csrc, cnorm, dinv, bufA, N);
    gemm_kernel<true, true><<<gemm_grid(N, 216), 256>>>(bufA, W3, b3, bufB, N, 108, 216);

    // --- Global mean pool ---
    pool_kernel<<<G, 224>>>(bufB, batch, pooled, N, 216);

    // --- MLP head ---
    gemm_kernel<true, true><<<gemm_grid(G, 1024), 256>>>(pooled, Wf1, bf1, fc1, G, 216, 1024);
    gemm_kernel<false, true><<<gemm_grid(G, 128), 256>>>(fc1, Wf2, bf2, (float*)d_out, G, 1024, 128);
}

// round 3
// speedup vs baseline: 2.4196x; 1.1324x over previous
#include <cuda_runtime.h>
#include <cuda_bf16.h>

#define MAX_N 100000
#define MAX_E 1600000
#define MAX_G 256
#define SCAN_T 256
#define MAX_BLOCKS ((MAX_N + SCAN_T - 1) / SCAN_T)   // 391

// ---------------------------------------------------------------------------
// Static scratch
// ---------------------------------------------------------------------------
__device__ float g_bufA[MAX_N * 216];
__device__ float g_bufB[MAX_N * 216];
__device__ float g_dinv[MAX_N];
__device__ float g_pooled[MAX_G * 216];
__device__ float g_fc1[MAX_G * 1024];
__device__ int   g_counts[MAX_N];
__device__ int   g_indptr[MAX_N + 1];
__device__ int   g_cursor[MAX_N];
__device__ int   g_blockSums[MAX_BLOCKS];
__device__ int   g_csrc[MAX_E];
__device__ float g_cnorm[MAX_E];

// ---------------------------------------------------------------------------
// CSR construction
// ---------------------------------------------------------------------------
__global__ void zero_counts_kernel(int* counts, int N) {
    int i = blockIdx.x * blockDim.x + threadIdx.x;
    if (i < N) counts[i] = 0;
}

__global__ void count_kernel(const int* __restrict__ col, int* counts, int E) {
    int i = blockIdx.x * blockDim.x + threadIdx.x;
    if (i < E) atomicAdd(&counts[col[i]], 1);
}

__global__ void dinv_kernel(const int* __restrict__ counts, float* __restrict__ dinv, int N) {
    int i = blockIdx.x * blockDim.x + threadIdx.x;
    if (i < N) dinv[i] = rsqrtf((float)(counts[i] + 1));  // +1 self-loop
}

// Phase A: per-block sums of counts
__global__ void block_sum_kernel(const int* __restrict__ counts, int* __restrict__ blockSums, int N) {
    __shared__ int s[SCAN_T];
    int i = blockIdx.x * SCAN_T + threadIdx.x;
    s[threadIdx.x] = (i < N) ? counts[i] : 0;
    __syncthreads();
    #pragma unroll
    for (int off = SCAN_T / 2; off > 0; off >>= 1) {
        if (threadIdx.x < off) s[threadIdx.x] += s[threadIdx.x + off];
        __syncthreads();
    }
    if (threadIdx.x == 0) blockSums[blockIdx.x] = s[0];
}

// Phase B: exclusive scan of block sums (nb <= 1024) in one block
__global__ void scan_partials_kernel(int* blockSums, int nb) {
    __shared__ int s[1024];
    int t = threadIdx.x;
    int v = (t < nb) ? blockSums[t] : 0;
    s[t] = v;
    __syncthreads();
    #pragma unroll
    for (int off = 1; off < 1024; off <<= 1) {
        int u = (t >= off) ? s[t - off] : 0;
        __syncthreads();
        s[t] += u;
        __syncthreads();
    }
    if (t < nb) blockSums[t] = s[t] - v;  // exclusive
}

// Phase C: per-block inclusive scan + global offset -> indptr/cursor
__global__ void scan_write_kernel(const int* __restrict__ counts, const int* __restrict__ blockSums,
                                  int* __restrict__ indptr, int* __restrict__ cursor, int N) {
    __shared__ int s[SCAN_T];
    int i = blockIdx.x * SCAN_T + threadIdx.x;
    int v = (i < N) ? counts[i] : 0;
    s[threadIdx.x] = v;
    __syncthreads();
    #pragma unroll
    for (int off = 1; off < SCAN_T; off <<= 1) {
        int u = (threadIdx.x >= off) ? s[threadIdx.x - off] : 0;
        __syncthreads();
        s[threadIdx.x] += u;
        __syncthreads();
    }
    int excl = blockSums[blockIdx.x] + s[threadIdx.x] - v;
    if (i < N) { indptr[i] = excl; cursor[i] = excl; }
    if (i == N - 1) indptr[N] = excl + v;
}

__global__ void fill_kernel(const int* __restrict__ row, const int* __restrict__ col,
                            const float* __restrict__ dinv, int* cursor,
                            int* __restrict__ csrc, float* __restrict__ cnorm, int E) {
    int e = blockIdx.x * blockDim.x + threadIdx.x;
    if (e >= E) return;
    int r = row[e], c = col[e];
    int pos = atomicAdd(&cursor[c], 1);
    csrc[pos] = r;
    cnorm[pos] = dinv[r] * dinv[c];
}

// ---------------------------------------------------------------------------
// CSR gather aggregation, one warp per node, 4 ILP chains.
// ---------------------------------------------------------------------------
__global__ void gather54_kernel(const float* __restrict__ h, const int* __restrict__ indptr,
                                const int* __restrict__ csrc, const float* __restrict__ cnorm,
                                const float* __restrict__ dinv, float* __restrict__ out, int N) {
    const int F = 54, NL = 27;
    int warp = (blockIdx.x * blockDim.x + threadIdx.x) >> 5;
    int lane = threadIdx.x & 31;
    if (warp >= N) return;
    int v = warp;
    int s = indptr[v], e = indptr[v + 1];
    float2 a0 = {0.f, 0.f}, a1 = {0.f, 0.f}, a2 = {0.f, 0.f}, a3 = {0.f, 0.f};
    bool act = lane < NL;
    size_t off2 = (size_t)lane * 2;
    int i = s;
    for (; i + 3 < e; i += 4) {
        int s0 = csrc[i], s1 = csrc[i + 1], s2 = csrc[i + 2], s3 = csrc[i + 3];
        float n0 = cnorm[i], n1 = cnorm[i + 1], n2 = cnorm[i + 2], n3 = cnorm[i + 3];
        if (act) {
            float2 x0 = *reinterpret_cast<const float2*>(h + (size_t)s0 * F + off2);
            float2 x1 = *reinterpret_cast<const float2*>(h + (size_t)s1 * F + off2);
            float2 x2 = *reinterpret_cast<const float2*>(h + (size_t)s2 * F + off2);
            float2 x3 = *reinterpret_cast<const float2*>(h + (size_t)s3 * F + off2);
            a0.x += n0 * x0.x; a0.y += n0 * x0.y;
            a1.x += n1 * x1.x; a1.y += n1 * x1.y;
            a2.x += n2 * x2.x; a2.y += n2 * x2.y;
            a3.x += n3 * x3.x; a3.y += n3 * x3.y;
        }
    }
    for (; i < e; i++) {
        int s0 = csrc[i];
        float n0 = cnorm[i];
        if (act) {
            float2 x0 = *reinterpret_cast<const float2*>(h + (size_t)s0 * F + off2);
            a0.x += n0 * x0.x; a0.y += n0 * x0.y;
        }
    }
    if (act) {
        float d = dinv[v]; float dd = d * d;
        float2 xv = *reinterpret_cast<const float2*>(h + (size_t)v * F + off2);
        float2 r;
        r.x = (a0.x + a1.x) + (a2.x + a3.x) + dd * xv.x;
        r.y = (a0.y + a1.y) + (a2.y + a3.y) + dd * xv.y;
        *reinterpret_cast<float2*>(out + (size_t)v * F + off2) = r;
    }
}

__global__ void gather108_kernel(const float* __restrict__ h, const int* __restrict__ indptr,
                                 const int* __restrict__ csrc, const float* __restrict__ cnorm,
                                 const float* __restrict__ dinv, float* __restrict__ out, int N) {
    const int F = 108, NL = 27;
    int warp = (blockIdx.x * blockDim.x + threadIdx.x) >> 5;
    int lane = threadIdx.x & 31;
    if (warp >= N) return;
    int v = warp;
    int s = indptr[v], e = indptr[v + 1];
    float4 a0 = {0.f, 0.f, 0.f, 0.f}, a1 = {0.f, 0.f, 0.f, 0.f};
    float4 a2 = {0.f, 0.f, 0.f, 0.f}, a3 = {0.f, 0.f, 0.f, 0.f};
    bool act = lane < NL;
    size_t off4 = (size_t)lane * 4;
    int i = s;
    for (; i + 3 < e; i += 4) {
        int s0 = csrc[i], s1 = csrc[i + 1], s2 = csrc[i + 2], s3 = csrc[i + 3];
        float n0 = cnorm[i], n1 = cnorm[i + 1], n2 = cnorm[i + 2], n3 = cnorm[i + 3];
        if (act) {
            float4 x0 = *reinterpret_cast<const float4*>(h + (size_t)s0 * F + off4);
            float4 x1 = *reinterpret_cast<const float4*>(h + (size_t)s1 * F + off4);
            float4 x2 = *reinterpret_cast<const float4*>(h + (size_t)s2 * F + off4);
            float4 x3 = *reinterpret_cast<const float4*>(h + (size_t)s3 * F + off4);
            a0.x += n0 * x0.x; a0.y += n0 * x0.y; a0.z += n0 * x0.z; a0.w += n0 * x0.w;
            a1.x += n1 * x1.x; a1.y += n1 * x1.y; a1.z += n1 * x1.z; a1.w += n1 * x1.w;
            a2.x += n2 * x2.x; a2.y += n2 * x2.y; a2.z += n2 * x2.z; a2.w += n2 * x2.w;
            a3.x += n3 * x3.x; a3.y += n3 * x3.y; a3.z += n3 * x3.z; a3.w += n3 * x3.w;
        }
    }
    for (; i < e; i++) {
        int s0 = csrc[i];
        float n0 = cnorm[i];
        if (act) {
            float4 x0 = *reinterpret_cast<const float4*>(h + (size_t)s0 * F + off4);
            a0.x += n0 * x0.x; a0.y += n0 * x0.y; a0.z += n0 * x0.z; a0.w += n0 * x0.w;
        }
    }
    if (act) {
        float d = dinv[v]; float dd = d * d;
        float4 xv = *reinterpret_cast<const float4*>(h + (size_t)v * F + off4);
        float4 r;
        r.x = (a0.x + a1.x) + (a2.x + a3.x) + dd * xv.x;
        r.y = (a0.y + a1.y) + (a2.y + a3.y) + dd * xv.y;
        r.z = (a0.z + a1.z) + (a2.z + a3.z) + dd * xv.z;
        r.w = (a0.w + a1.w) + (a2.w + a3.w) + dd * xv.w;
        *reinterpret_cast<float4*>(out + (size_t)v * F + off4) = r;
    }
}

// ---------------------------------------------------------------------------
// Tiled SGEMM: 128x64x16 tile, 8x4 microtile, 256 threads.
// C = A[M,K] @ B[K,Nc] (+bias)(+relu)
// ---------------------------------------------------------------------------
template <bool RELU_OUT, bool BIAS>
__global__ void gemm_kernel(const float* __restrict__ A, const float* __restrict__ B,
                            const float* __restrict__ bias, float* __restrict__ C,
                            int M, int K, int Nc) {
    const int BM = 128, BN = 64, BK = 16;
    __shared__ __align__(16) float As[BK][BM];
    __shared__ __align__(16) float Bs[BK][BN];

    int block_row = blockIdx.y * BM;
    int block_col = blockIdx.x * BN;
    int tid = threadIdx.x;
    int tr = tid / 16;   // 0..15 -> rows tr*8 .. tr*8+7
    int tc = tid % 16;   // 0..15 -> cols tc*4 .. tc*4+3

    float acc[8][4] = {};

    for (int k0 = 0; k0 < K; k0 += BK) {
        #pragma unroll
        for (int i = tid; i < BM * BK; i += 256) {
            int r = i / BK, c = i % BK;
            int gr = block_row + r, gk = k0 + c;
            As[c][r] = (gr < M && gk < K) ? A[(size_t)gr * K + gk] : 0.f;
        }
        #pragma unroll
        for (int i = tid; i < BK * BN; i += 256) {
            int r = i / BN, c = i % BN;
            int gk = k0 + r, gc = block_col + c;
            Bs[r][c] = (gk < K && gc < Nc) ? B[(size_t)gk * Nc + gc] : 0.f;
        }
        __syncthreads();

        #pragma unroll
        for (int k = 0; k < BK; k++) {
            float4 alo = *reinterpret_cast<const float4*>(&As[k][tr * 8]);
            float4 ahi = *reinterpret_cast<const float4*>(&As[k][tr * 8 + 4]);
            float4 b   = *reinterpret_cast<const float4*>(&Bs[k][tc * 4]);
            float av[8] = {alo.x, alo.y, alo.z, alo.w, ahi.x, ahi.y, ahi.z, ahi.w};
            float bv[4] = {b.x, b.y, b.z, b.w};
            #pragma unroll
            for (int i = 0; i < 8; i++)
                #pragma unroll
                for (int j = 0; j < 4; j++)
                    acc[i][j] += av[i] * bv[j];
        }
        __syncthreads();
    }

    #pragma unroll
    for (int i = 0; i < 8; i++) {
        int gr = block_row + tr * 8 + i;
        if (gr >= M) continue;
        #pragma unroll
        for (int j = 0; j < 4; j++) {
            int gc = block_col + tc * 4 + j;
            if (gc >= Nc) continue;
            float v = acc[i][j];
            if (BIAS) v += bias[gc];
            if (RELU_OUT) v = fmaxf(v, 0.f);
            C[(size_t)gr * Nc + gc] = v;
        }
    }
}

// ---------------------------------------------------------------------------
// Per-graph mean pool. One block per graph, sorted batch.
// ---------------------------------------------------------------------------
__global__ void pool_kernel(const float* __restrict__ h, const int* __restrict__ batch,
                            float* __restrict__ pooled, int N, int F) {
    int g = blockIdx.x;
    int lo = 0, hi = N;
    while (lo < hi) { int m = (lo + hi) >> 1; if (batch[m] < g) lo = m + 1; else hi = m; }
    int start = lo;
    lo = start; hi = N;
    while (lo < hi) { int m = (lo + hi) >> 1; if (batch[m] < g + 1) lo = m + 1; else hi = m; }
    int end = lo;

    int f = threadIdx.x;
    if (f >= F) return;
    float acc = 0.f;
    for (int v = start; v < end; v++)
        acc += h[(size_t)v * F + f];
    float cnt = (float)(end - start);
    pooled[g * F + f] = acc / fmaxf(cnt, 1.0f);
}

// ---------------------------------------------------------------------------
// Launch
// ---------------------------------------------------------------------------
static inline dim3 gemm_grid(int M, int Nc) {
    return dim3((Nc + 63) / 64, (M + 127) / 128);
}

extern "C" void kernel_launch(void* const* d_in, const int* in_sizes, int n_in,
                              void* d_out, int out_size) {
    const float* x    = (const float*)d_in[0];
    const int*   ei   = (const int*)d_in[1];
    const int*   batch= (const int*)d_in[2];
    const float* W1   = (const float*)d_in[3];
    const float* b1   = (const float*)d_in[4];
    const float* W2   = (const float*)d_in[5];
    const float* b2   = (const float*)d_in[6];
    const float* W3   = (const float*)d_in[7];
    const float* b3   = (const float*)d_in[8];
    const float* Wf1  = (const float*)d_in[9];
    const float* bf1  = (const float*)d_in[10];
    const float* Wf2  = (const float*)d_in[11];
    const float* bf2  = (const float*)d_in[12];

    int N = in_sizes[0] / 54;
    int E = in_sizes[1] / 2;
    int G = out_size / 128;
    const int* row = ei;
    const int* col = ei + E;

    float *bufA, *bufB, *dinv, *pooled, *fc1, *cnorm;
    int *counts, *indptr, *cursor, *csrc, *blockSums;
    cudaGetSymbolAddress((void**)&bufA, g_bufA);
    cudaGetSymbolAddress((void**)&bufB, g_bufB);
    cudaGetSymbolAddress((void**)&dinv, g_dinv);
    cudaGetSymbolAddress((void**)&pooled, g_pooled);
    cudaGetSymbolAddress((void**)&fc1, g_fc1);
    cudaGetSymbolAddress((void**)&counts, g_counts);
    cudaGetSymbolAddress((void**)&indptr, g_indptr);
    cudaGetSymbolAddress((void**)&cursor, g_cursor);
    cudaGetSymbolAddress((void**)&csrc, g_csrc);
    cudaGetSymbolAddress((void**)&cnorm, g_cnorm);
    cudaGetSymbolAddress((void**)&blockSums, g_blockSums);

    const int T = 256;
    int nb = (N + SCAN_T - 1) / SCAN_T;
    int gatherGrid = (N + 7) / 8;

    // --- CSR build + normalization ---
    zero_counts_kernel<<<(N + T - 1) / T, T>>>(counts, N);
    count_kernel<<<(E + T - 1) / T, T>>>(col, counts, E);
    dinv_kernel<<<(N + T - 1) / T, T>>>(counts, dinv, N);
    block_sum_kernel<<<nb, SCAN_T>>>(counts, blockSums, N);
    scan_partials_kernel<<<1, 1024>>>(blockSums, nb);
    scan_write_kernel<<<nb, SCAN_T>>>(counts, blockSums, indptr, cursor, N);
    fill_kernel<<<(E + T - 1) / T, T>>>(row, col, dinv, cursor, csrc, cnorm, E);

    // --- Layer 1 ---
    gather54_kernel<<<gatherGrid, T>>>(x, indptr, csrc, cnorm, dinv, bufA, N);
    gemm_kernel<true, true><<<gemm_grid(N, 54), 256>>>(bufA, W1, b1, bufB, N, 54, 54);

    // --- Layer 2 ---
    gather54_kernel<<<gatherGrid, T>>>(bufB, indptr, csrc, cnorm, dinv, bufA, N);
    gemm_kernel<true, true><<<gemm_grid(N, 108), 256>>>(bufA, W2, b2, bufB, N, 54, 108);

    // --- Layer 3 ---
    gather108_kernel<<<gatherGrid, T>>>(bufB, indptr, csrc, cnorm, dinv, bufA, N);
    gemm_kernel<true, true><<<gemm_grid(N, 216), 256>>>(bufA, W3, b3, bufB, N, 108, 216);

    // --- Global mean pool ---
    pool_kernel<<<G, 224>>>(bufB, batch, pooled, N, 216);

    // --- MLP head ---
    gemm_kernel<true, true><<<gemm_grid(G, 1024), 256>>>(pooled, Wf1, bf1, fc1, G, 216, 1024);
    gemm_kernel<false, true><<<gemm_grid(G, 128), 256>>>(fc1, Wf2, bf2, (float*)d_out, G, 1024, 128);
}